// round 16
// baseline (speedup 1.0000x reference)
#include <cuda_runtime.h>
#include <cuda_fp16.h>
#include <math.h>
#include <stdint.h>

#define BATCH 64
#define CH    128
#define LEN   1024
#define ROWS  (BATCH*CH)          /* 8192  */
#define FEAT  (CH*LEN)            /* 131072 */
#define NELEM (BATCH*CH*LEN)      /* 8388608 */

/* ---------------- scratch (static device globals; allocation-free) -------- */
__device__ float  g_xn[NELEM];
__device__ __half g_trend1[NELEM];
__device__ __half g_d8[2 * ROWS * 128];
__device__ __half g_d4[2 * ROWS * 256];
__device__ __half g_d2[2 * ROWS * 512];
__device__ __half g_h8[2 * ROWS * LEN];
__device__ __half g_h4[2 * ROWS * LEN];
__device__ __half g_h2[2 * ROWS * LEN];
__device__ __half g_o8[2 * ROWS * LEN];        /* [up ; trend], half          */
__device__ __half g_o4[2 * ROWS * LEN];
__device__ __half g_o2[2 * ROWS * LEN];
__device__ float  g_means[5 * ROWS];     /* [mdiff8|mdiff4|mdiff2|sx1|sy1]   */
__device__ float  g_gates[BATCH * 4];
__device__ float  g_wbar[3 * 1024];      /* col-means of w2 (incl 1/L)       */
__device__ __half g_w1h[1024 * (512 + 256 + 128)];
__device__ __half g_w2h[3 * 1024 * 1024];

/* ------ prep: weights->half, zero mdiff, wbar (block-range dispatch) ------- */
#define NW_TOTAL (1024*(512+256+128) + 3*1024*1024)      /* 4063232 */
#define PREP_CONV_BLOCKS ((NW_TOTAL + 255) / 256)        /* 15872   */
#define PREP_WBAR_BLOCKS 12
__global__ void prep_kernel(const float* __restrict__ w18, const float* __restrict__ w14,
                            const float* __restrict__ w12, const float* __restrict__ w28,
                            const float* __restrict__ w24, const float* __restrict__ w22) {
    if (blockIdx.x >= PREP_CONV_BLOCKS) {
        int kk = (blockIdx.x - PREP_CONV_BLOCKS) * 256 + threadIdx.x;
        int br = kk >> 10;
        int k  = kk & 1023;
        const float* w = (br == 0) ? w28 : (br == 1) ? w24 : w22;
        float s = 0.f;
        for (int l = 0; l < 1024; l++) s += w[l * 1024 + k];
        g_wbar[kk] = s * (1.f / 1024.f);
        return;
    }
    int i = blockIdx.x * blockDim.x + threadIdx.x;
    if (i < 3 * ROWS) g_means[i] = 0.f;
    if (i >= NW_TOTAL) return;
    float v;
    int j = i;
    __half* dst;
    if (j < 131072)            { v = w18[j];            dst = g_w1h + j; }
    else if (j < 393216)       { v = w14[j - 131072];   dst = g_w1h + j; }
    else if (j < 917504)       { v = w12[j - 393216];   dst = g_w1h + j; }
    else if (j < 1966080)      { v = w28[j - 917504];   dst = g_w2h + (j - 917504); }
    else if (j < 3014656)      { v = w24[j - 1966080];  dst = g_w2h + (j - 917504); }
    else                       { v = w22[j - 3014656];  dst = g_w2h + (j - 917504); }
    *dst = __float2half_rn(v);
}

/* ---------------- BatchNorm over batch axis ------------------------------- */
__global__ void bn_kernel(const float* __restrict__ x,
                          const float* __restrict__ gam,
                          const float* __restrict__ bet) {
    int f = blockIdx.x * blockDim.x + threadIdx.x;
    if (f >= FEAT) return;
    float v[BATCH];
    float s = 0.f;
#pragma unroll
    for (int b = 0; b < BATCH; b++) { v[b] = x[(size_t)b * FEAT + f]; s += v[b]; }
    float mu = s * (1.f / BATCH);
    float q = 0.f;
#pragma unroll
    for (int b = 0; b < BATCH; b++) { float d = v[b] - mu; q += d * d; }
    float inv = rsqrtf(q * (1.f / BATCH) + 1e-5f);
    float gg = gam[f] * inv, bb = bet[f];
#pragma unroll
    for (int b = 0; b < BATCH; b++)
        g_xn[(size_t)b * FEAT + f] = (v[b] - mu) * gg + bb;
}

/* ---------------- fused depthwise conv, smem-staged ------------------------ */
__global__ void __launch_bounds__(256)
dwconv_all_kernel(const float* __restrict__ xn,
                  const float* __restrict__ cw8,
                  const float* __restrict__ cw4,
                  const float* __restrict__ cw2,
                  __half* __restrict__ o8,
                  __half* __restrict__ o4,
                  __half* __restrict__ o2) {
    __shared__ float sx[2][LEN + 16];
    const int tid = threadIdx.x;
    const int r   = tid >> 7;
    const int t8  = tid & 127;
    const int row = blockIdx.x * 2 + r;
    const int c   = row & (CH - 1);

    {
        const float4* src = (const float4*)(xn + (size_t)row * LEN);
        float4* dstv = (float4*)(sx[r] + 4);
#pragma unroll
        for (int q = 0; q < 2; q++)
            dstv[t8 + q * 128] = src[t8 + q * 128];
        if (t8 < 4)  sx[r][t8] = 0.f;
        if (t8 < 12) sx[r][LEN + 4 + t8] = 0.f;
    }
    __syncthreads();

    const float* w = sx[r] + t8 * 8;
    {
        const float* cf = cw8 + c * 16;
        float acc = 0.f;
#pragma unroll
        for (int k = 0; k < 16; k++) acc = fmaf(w[k], cf[k], acc);
        o8[(size_t)row * 128 + t8] = __float2half_rn(acc);
    }
    {
        const float* cf = cw4 + c * 8;
#pragma unroll
        for (int i = 0; i < 2; i++) {
            float acc = 0.f;
#pragma unroll
            for (int k = 0; k < 8; k++) acc = fmaf(w[2 + 4 * i + k], cf[k], acc);
            o4[(size_t)row * 256 + 2 * t8 + i] = __float2half_rn(acc);
        }
    }
    {
        const float* cf = cw2 + c * 4;
#pragma unroll
        for (int i = 0; i < 4; i++) {
            float acc = 0.f;
#pragma unroll
            for (int k = 0; k < 4; k++) acc = fmaf(w[3 + 2 * i + k], cf[k], acc);
            o2[(size_t)row * 512 + 4 * t8 + i] = __float2half_rn(acc);
        }
    }
}

/* ------------ EMA: segment-serial prefix + ADDITIVE exclusive scan --------- */
template <typename TI, typename TO, int LS>
__global__ void ema_kernel(const TI* __restrict__ src,
                           TO* __restrict__ dst,
                           const float* __restrict__ al,
                           float* __restrict__ sumx, float* __restrict__ sumy) {
    constexpr int E = LS / 32;
    int warp = (blockIdx.x * blockDim.x + threadIdx.x) >> 5;
    int lane = threadIdx.x & 31;
    if (warp >= ROWS) return;
    int c = warp % CH;
    float a  = 1.f / (1.f + expf(-al[c]));
    float om = 1.f - a;
    float l2 = log2f(om);
    float inva = 1.f / a;
    float K0 = exp2f((float)LS * l2);
    const int jb = lane * E;
    const TI* x = src + (size_t)warp * LS + jb;
    TO* y       = dst + (size_t)warp * LS + jb;

    float xv[E];
    float tot = 0.f, sx = 0.f;
#pragma unroll
    for (int i = 0; i < E; i++) {
        xv[i] = (float)x[i];
        float base = exp2f((float)(LS - 1 - jb - i) * l2);
        float wn = (jb + i == 0) ? base : base * a;
        tot = fmaf(xv[i], wn, tot);
        sx += xv[i];
    }
    /* inclusive scan of totals, then ADDITIVE exclusive via shift-up-1
       (never t - tot: geometric weight growth makes that catastrophically
       cancel) */
    float t = tot;
#pragma unroll
    for (int o = 1; o < 32; o <<= 1) {
        float v = __shfl_up_sync(0xffffffffu, t, o);
        if (lane >= o) t += v;
    }
    float run = __shfl_up_sync(0xffffffffu, t, 1);
    if (lane == 0) run = 0.f;
    float sy = 0.f;
#pragma unroll
    for (int i = 0; i < E; i++) {
        float base = exp2f((float)(LS - 1 - jb - i) * l2);
        float wn = (jb + i == 0) ? base : base * a;
        run = fmaf(xv[i], wn, run);
        float den = fmaxf((base - K0) * inva, 1e-12f);
        float yv = run / den;
        y[i] = (TO)yv;
        sy += yv;
    }
    if (sumx) {
#pragma unroll
        for (int o = 16; o > 0; o >>= 1) {
            sx += __shfl_xor_sync(0xffffffffu, sx, o);
            sy += __shfl_xor_sync(0xffffffffu, sy, o);
        }
        if (lane == 0) { sumx[warp] = sx; sumy[warp] = sy; }
    }
}

/* =================== shared GEMM machinery ================================== */
#define PITCH_H 72
#define PITCH_B 144
#define BKH 64
#define MAT_STAGE_B 18432
#define B_OFF 36864
#define GEMM_SMEM_B 73728

__device__ __forceinline__ uint32_t smem_u32(const void* p) {
    uint32_t a;
    asm("{.reg .u64 t; cvta.to.shared.u64 t, %1; cvt.u32.u64 %0, t;}"
        : "=r"(a) : "l"(p));
    return a;
}
__device__ __forceinline__ void cp_async16(uint32_t saddr, const void* g) {
    asm volatile("cp.async.cg.shared.global [%0], [%1], 16;"
                 :: "r"(saddr), "l"(g));
}
#define LDSM4(r0, r1, r2, r3, addr) \
    asm volatile("ldmatrix.sync.aligned.m8n8.x4.shared.b16 {%0,%1,%2,%3}, [%4];" \
                 : "=r"(r0), "=r"(r1), "=r"(r2), "=r"(r3) : "r"(addr))

__device__ __forceinline__ void mma_f16(float* d,
                                        const uint32_t* a, const uint32_t* b,
                                        const float* c) {
    asm volatile(
        "mma.sync.aligned.m16n8k16.row.col.f32.f16.f16.f32 "
        "{%0,%1,%2,%3}, {%4,%5,%6,%7}, {%8,%9}, {%10,%11,%12,%13};"
        : "=f"(d[0]), "=f"(d[1]), "=f"(d[2]), "=f"(d[3])
        : "r"(a[0]), "r"(a[1]), "r"(a[2]), "r"(a[3]),
          "r"(b[0]), "r"(b[1]),
          "f"(c[0]), "f"(c[1]), "f"(c[2]), "f"(c[3]));
}

__device__ __forceinline__ float gelu_exact(float v) {
    return 0.5f * v * (1.f + erff(v * 0.70710678118654752f));
}

__device__ __forceinline__ void mma_step(const uint32_t aa, const uint32_t bb,
                                         float acc[2][8][4]) {
#pragma unroll
    for (int kk = 0; kk < 4; kk++) {
        const uint32_t kb = kk * 32;
        uint32_t af[2][4], bf[8][2];
        LDSM4(af[0][0], af[0][1], af[0][2], af[0][3], aa + kb);
        LDSM4(af[1][0], af[1][1], af[1][2], af[1][3], aa + kb + 16 * PITCH_B);
#pragma unroll
        for (int p = 0; p < 4; p++) {
            uint32_t q0, q1, q2, q3;
            LDSM4(q0, q1, q2, q3, bb + kb + p * 16 * PITCH_B);
            bf[2 * p][0] = q0; bf[2 * p + 1][0] = q1;
            bf[2 * p][1] = q2; bf[2 * p + 1][1] = q3;
        }
#pragma unroll
        for (int mt = 0; mt < 2; mt++)
#pragma unroll
            for (int nt = 0; nt < 8; nt++)
                mma_f16(acc[mt][nt], af[mt], bf[nt], acc[mt][nt]);
    }
}

#define GEMM_MAINLOOP(src, sldbase, a_ab, b_ab, niter, acc)                     \
    do {                                                                        \
        _Pragma("unroll")                                                       \
        for (int c = 0; c < 8; c++)                                             \
            cp_async16((sldbase) + c * 16, (src) + c * 8);                      \
        asm volatile("cp.async.commit_group;");                                 \
        for (int i = 0; i < (niter); i++) {                                     \
            asm volatile("cp.async.wait_group 0;");                             \
            __syncthreads();                                                    \
            if (i + 1 < (niter)) {                                              \
                const __half* gsrc = (src) + (i + 1) * BKH;                     \
                uint32_t d = ((i + 1) & 1) * MAT_STAGE_B;                       \
                _Pragma("unroll")                                               \
                for (int c = 0; c < 8; c++)                                     \
                    cp_async16((sldbase) + d + c * 16, gsrc + c * 8);           \
                asm volatile("cp.async.commit_group;");                         \
            }                                                                   \
            const uint32_t stg = (i & 1) * MAT_STAGE_B;                         \
            mma_step((a_ab) + stg, (b_ab) + stg, acc);                          \
        }                                                                       \
    } while (0)

/* ============ GEMM1: h = gelu(A·W1^T + b1), + signed w̄2 row-reduce ========= */
__global__ void __launch_bounds__(256, 2)
gemm1_kernel(const __half* __restrict__ A, const __half* __restrict__ B,
             __half* __restrict__ Cout, const float* __restrict__ bias,
             int K, float* __restrict__ mdiff, const float* __restrict__ wbar) {
    extern __shared__ char smem[];
    const uint32_t sb = smem_u32(smem);
    const int tid  = threadIdx.x;
    const int wid  = tid >> 5;
    const int lane = tid & 31;
    const int g    = lane >> 2;
    const int tg   = lane & 3;
    const int wm   = (wid >> 1) * 32;
    const int wn   = (wid & 1) * 64;
    const int m0 = blockIdx.y * 128, n0 = blockIdx.x * 128;

    const int mat = tid >> 7, row = tid & 127;
    const __half* src = mat ? (B + (size_t)(n0 + row) * K)
                            : (A + (size_t)(m0 + row) * K);
    const uint32_t sldbase = sb + mat * B_OFF + row * PITCH_B;

    const int lr16 = lane & 15;
    const int lhi  = (lane >> 4) << 3;
    const uint32_t a_ab = sb + ((wm + lr16) * PITCH_H + lhi) * 2;
    const uint32_t b_ab = sb + B_OFF + ((wn + lr16) * PITCH_H + lhi) * 2;

    float acc[2][8][4];
#pragma unroll
    for (int i = 0; i < 2; i++)
#pragma unroll
        for (int j = 0; j < 8; j++)
#pragma unroll
            for (int q = 0; q < 4; q++) acc[i][j][q] = 0.f;

    const int niter = K / BKH;
    GEMM_MAINLOOP(src, sldbase, a_ab, b_ab, niter, acc);

#pragma unroll
    for (int mt = 0; mt < 2; mt++) {
        int r0 = m0 + wm + mt * 16 + g;
        float sgn = (r0 < ROWS) ? 1.f : -1.f;
        int srow = r0 & (ROWS - 1);
        float d0 = 0.f, d1 = 0.f;
#pragma unroll
        for (int nt = 0; nt < 8; nt++) {
            int c0 = n0 + wn + nt * 8 + 2 * tg;
            float b0 = bias[c0], b1 = bias[c0 + 1];
            float v0 = gelu_exact(acc[mt][nt][0] + b0);
            float v1 = gelu_exact(acc[mt][nt][1] + b1);
            float v2 = gelu_exact(acc[mt][nt][2] + b0);
            float v3 = gelu_exact(acc[mt][nt][3] + b1);
            float wb0 = wbar[c0], wb1 = wbar[c0 + 1];
            d0 += wb0 * v0 + wb1 * v1;
            d1 += wb0 * v2 + wb1 * v3;
            *(__half2*)(Cout + (size_t)r0 * 1024 + c0)       = __floats2half2_rn(v0, v1);
            *(__half2*)(Cout + (size_t)(r0 + 8) * 1024 + c0) = __floats2half2_rn(v2, v3);
        }
        d0 += __shfl_xor_sync(0xffffffffu, d0, 1);
        d0 += __shfl_xor_sync(0xffffffffu, d0, 2);
        d1 += __shfl_xor_sync(0xffffffffu, d1, 1);
        d1 += __shfl_xor_sync(0xffffffffu, d1, 2);
        if (tg == 0) {
            atomicAdd(&mdiff[srow],     sgn * d0);
            atomicAdd(&mdiff[srow + 8], sgn * d1);
        }
    }
}

/* ============ GEMM2: o = A·W2^T + b2  (half out) ============================ */
__global__ void __launch_bounds__(256, 2)
gemm2_kernel(const __half* __restrict__ A, const __half* __restrict__ B,
             __half* __restrict__ Cout, const float* __restrict__ bias) {
    extern __shared__ char smem[];
    const uint32_t sb = smem_u32(smem);
    const int tid  = threadIdx.x;
    const int wid  = tid >> 5;
    const int lane = tid & 31;
    const int g    = lane >> 2;
    const int tg   = lane & 3;
    const int wm   = (wid >> 1) * 32;
    const int wn   = (wid & 1) * 64;
    const int m0 = blockIdx.y * 128, n0 = blockIdx.x * 128;
    const int K = 1024;

    const int mat = tid >> 7, row = tid & 127;
    const __half* src = mat ? (B + (size_t)(n0 + row) * K)
                            : (A + (size_t)(m0 + row) * K);
    const uint32_t sldbase = sb + mat * B_OFF + row * PITCH_B;

    const int lr16 = lane & 15;
    const int lhi  = (lane >> 4) << 3;
    const uint32_t a_ab = sb + ((wm + lr16) * PITCH_H + lhi) * 2;
    const uint32_t b_ab = sb + B_OFF + ((wn + lr16) * PITCH_H + lhi) * 2;

    float acc[2][8][4];
#pragma unroll
    for (int i = 0; i < 2; i++)
#pragma unroll
        for (int j = 0; j < 8; j++)
#pragma unroll
            for (int q = 0; q < 4; q++) acc[i][j][q] = 0.f;

    GEMM_MAINLOOP(src, sldbase, a_ab, b_ab, 16, acc);

#pragma unroll
    for (int mt = 0; mt < 2; mt++) {
        int r0 = m0 + wm + mt * 16 + g;
#pragma unroll
        for (int nt = 0; nt < 8; nt++) {
            int c0 = n0 + wn + nt * 8 + 2 * tg;
            float b0 = bias[c0], b1 = bias[c0 + 1];
            *(__half2*)(Cout + (size_t)r0 * 1024 + c0) =
                __floats2half2_rn(acc[mt][nt][0] + b0, acc[mt][nt][1] + b1);
            *(__half2*)(Cout + (size_t)(r0 + 8) * 1024 + c0) =
                __floats2half2_rn(acc[mt][nt][2] + b0, acc[mt][nt][3] + b1);
        }
    }
}

/* ---------------- gates ----------------------------------------------------- */
__global__ void gate_kernel(const float* __restrict__ gw8, const float* __restrict__ gb8,
                            const float* __restrict__ gw4, const float* __restrict__ gb4,
                            const float* __restrict__ gw2, const float* __restrict__ gb2,
                            const float* __restrict__ gw1, const float* __restrict__ gb1) {
    int b = blockIdx.x;
    int c = threadIdx.x;
    __shared__ float red[4][128];
    int bc = b * CH + c;
    red[0][c] = g_means[bc] * gw8[c];
    red[1][c] = g_means[ROWS + bc] * gw4[c];
    red[2][c] = g_means[2 * ROWS + bc] * gw2[c];
    red[3][c] = (g_means[3 * ROWS + bc] - g_means[4 * ROWS + bc]) * (1.f / LEN) * gw1[c];
    __syncthreads();
    for (int o = 64; o > 0; o >>= 1) {
        if (c < o) {
            for (int s = 0; s < 4; s++) red[s][c] += red[s][c + o];
        }
        __syncthreads();
    }
    if (c == 0) {
        float gbv[4] = {gb8[0], gb4[0], gb2[0], gb1[0]};
        float gv[4], tot = 0.f;
        for (int s = 0; s < 4; s++) {
            gv[s] = 1.f / (1.f + expf(-(red[s][0] + gbv[s])));
            tot += gv[s];
        }
        for (int s = 0; s < 4; s++) g_gates[b * 4 + s] = gv[s] / (tot + 1e-6f);
    }
}

/* ---------------- vectorized combine: 8 elems/thread ----------------------- */
__global__ void combine_kernel(float* __restrict__ out) {
    size_t t = blockIdx.x * (size_t)blockDim.x + threadIdx.x;
    size_t i8 = t * 8;
    if (i8 >= NELEM) return;
    int b = (int)(i8 >> 10) / CH;
    const float* G = g_gates + b * 4;
    float g0 = G[0], g1 = G[1], g2 = G[2], g3 = G[3];

    const __half2* u8p = (const __half2*)(g_o8 + i8);
    const __half2* t8p = (const __half2*)(g_o8 + (size_t)NELEM + i8);
    const __half2* u4p = (const __half2*)(g_o4 + i8);
    const __half2* t4p = (const __half2*)(g_o4 + (size_t)NELEM + i8);
    const __half2* u2p = (const __half2*)(g_o2 + i8);
    const __half2* t2p = (const __half2*)(g_o2 + (size_t)NELEM + i8);
    const __half2* t1p = (const __half2*)(g_trend1 + i8);

    float x1[8];
    *(float4*)(x1)     = *(const float4*)(g_xn + i8);
    *(float4*)(x1 + 4) = *(const float4*)(g_xn + i8 + 4);

    float se[8], tr[8];
#pragma unroll
    for (int q = 0; q < 4; q++) {
        float2 u8v = __half22float2(u8p[q]);
        float2 t8v = __half22float2(t8p[q]);
        float2 u4v = __half22float2(u4p[q]);
        float2 t4v = __half22float2(t4p[q]);
        float2 u2v = __half22float2(u2p[q]);
        float2 t2v = __half22float2(t2p[q]);
        float2 t1v = __half22float2(t1p[q]);
        tr[2 * q]     = g0 * t8v.x + g1 * t4v.x + g2 * t2v.x + g3 * t1v.x;
        tr[2 * q + 1] = g0 * t8v.y + g1 * t4v.y + g2 * t2v.y + g3 * t1v.y;
        se[2 * q]     = g0 * (u8v.x - t8v.x) + g1 * (u4v.x - t4v.x)
                      + g2 * (u2v.x - t2v.x) + g3 * (x1[2 * q] - t1v.x);
        se[2 * q + 1] = g0 * (u8v.y - t8v.y) + g1 * (u4v.y - t4v.y)
                      + g2 * (u2v.y - t2v.y) + g3 * (x1[2 * q + 1] - t1v.y);
    }
    *(float4*)(out + i8)                       = *(float4*)(se);
    *(float4*)(out + i8 + 4)                   = *(float4*)(se + 4);
    *(float4*)(out + (size_t)NELEM + i8)       = *(float4*)(tr);
    *(float4*)(out + (size_t)NELEM + i8 + 4)   = *(float4*)(tr + 4);
}

/* ---------------- host orchestration -------------------------------------- */
extern "C" void kernel_launch(void* const* d_in, const int* in_sizes, int n_in,
                              void* d_out, int out_size) {
    const float* x    = (const float*)d_in[0];
    const float* bng  = (const float*)d_in[1];
    const float* bnb  = (const float*)d_in[2];
    const float* cw8  = (const float*)d_in[3];
    const float* w1_8 = (const float*)d_in[4];
    const float* b1_8 = (const float*)d_in[5];
    const float* w2_8 = (const float*)d_in[6];
    const float* b2_8 = (const float*)d_in[7];
    const float* cw4  = (const float*)d_in[8];
    const float* w1_4 = (const float*)d_in[9];
    const float* b1_4 = (const float*)d_in[10];
    const float* w2_4 = (const float*)d_in[11];
    const float* b2_4 = (const float*)d_in[12];
    const float* cw2  = (const float*)d_in[13];
    const float* w1_2 = (const float*)d_in[14];
    const float* b1_2 = (const float*)d_in[15];
    const float* w2_2 = (const float*)d_in[16];
    const float* b2_2 = (const float*)d_in[17];
    const float* gw8  = (const float*)d_in[18];
    const float* gb8  = (const float*)d_in[19];
    const float* al8  = (const float*)d_in[20];
    const float* gw4  = (const float*)d_in[21];
    const float* gb4  = (const float*)d_in[22];
    const float* al4  = (const float*)d_in[23];
    const float* gw2  = (const float*)d_in[24];
    const float* gb2  = (const float*)d_in[25];
    const float* al2  = (const float*)d_in[26];
    const float* gw1  = (const float*)d_in[27];
    const float* gb1  = (const float*)d_in[28];
    const float* al1  = (const float*)d_in[29];
    float* out = (float*)d_out;

    float *xn, *means, *wbar;
    __half *tr1, *d8, *d4, *d2, *h8, *h4, *h2, *o8, *o4, *o2, *w1h, *w2h;
    cudaGetSymbolAddress((void**)&xn,    g_xn);
    cudaGetSymbolAddress((void**)&tr1,   g_trend1);
    cudaGetSymbolAddress((void**)&d8,    g_d8);
    cudaGetSymbolAddress((void**)&d4,    g_d4);
    cudaGetSymbolAddress((void**)&d2,    g_d2);
    cudaGetSymbolAddress((void**)&h8,    g_h8);
    cudaGetSymbolAddress((void**)&h4,    g_h4);
    cudaGetSymbolAddress((void**)&h2,    g_h2);
    cudaGetSymbolAddress((void**)&o8,    g_o8);
    cudaGetSymbolAddress((void**)&o4,    g_o4);
    cudaGetSymbolAddress((void**)&o2,    g_o2);
    cudaGetSymbolAddress((void**)&means, g_means);
    cudaGetSymbolAddress((void**)&wbar,  g_wbar);
    cudaGetSymbolAddress((void**)&w1h,   g_w1h);
    cudaGetSymbolAddress((void**)&w2h,   g_w2h);

    __half* w1h8 = w1h;
    __half* w1h4 = w1h + 1024 * 128;
    __half* w1h2 = w1h + 1024 * (128 + 256);
    __half* w2h8 = w2h;
    __half* w2h4 = w2h + 1024 * 1024;
    __half* w2h2 = w2h + 2 * 1024 * 1024;

    cudaFuncSetAttribute(gemm1_kernel,
                         cudaFuncAttributeMaxDynamicSharedMemorySize, GEMM_SMEM_B);
    cudaFuncSetAttribute(gemm2_kernel,
                         cudaFuncAttributeMaxDynamicSharedMemorySize, GEMM_SMEM_B);

    static cudaStream_t st[3];
    static cudaEvent_t  ev0, evg[3], evb[3];
    static int sinit = 0;
    if (!sinit) {
        for (int i = 0; i < 3; i++)
            cudaStreamCreateWithFlags(&st[i], cudaStreamNonBlocking);
        cudaEventCreateWithFlags(&ev0, cudaEventDisableTiming);
        for (int i = 0; i < 3; i++) {
            cudaEventCreateWithFlags(&evg[i], cudaEventDisableTiming);
            cudaEventCreateWithFlags(&evb[i], cudaEventDisableTiming);
        }
        sinit = 1;
    }

    /* serial head on default stream (proven topology) */
    prep_kernel<<<PREP_CONV_BLOCKS + PREP_WBAR_BLOCKS, 256>>>(w1_8, w1_4, w1_2,
                                                              w2_8, w2_4, w2_2);
    bn_kernel<<<FEAT / 256, 256>>>(x, bng, bnb);
    dwconv_all_kernel<<<ROWS / 2, 256>>>(xn, cw8, cw4, cw2, d8, d4, d2);
    cudaEventRecord(ev0, 0);

    /* s=1 branch on main stream: trend1 + row sums of xn & trend1 */
    ema_kernel<float, __half, 1024><<<ROWS / 8, 256>>>(xn, tr1, al1,
                                                       means + 3 * ROWS,
                                                       means + 4 * ROWS);

    /* s = 8 on st[0] */
    cudaStreamWaitEvent(st[0], ev0, 0);
    {
        const int Ls = 128;
        ema_kernel<__half, __half, 128><<<ROWS / 8, 256, 0, st[0]>>>(d8, d8 + (size_t)ROWS * Ls, al8, 0, 0);
        gemm1_kernel<<<dim3(8, 128), 256, GEMM_SMEM_B, st[0]>>>(d8, w1h8, h8, b1_8, Ls,
                                                                means, wbar);
        cudaEventRecord(evg[0], st[0]);
        gemm2_kernel<<<dim3(8, 128), 256, GEMM_SMEM_B, st[0]>>>(h8, w2h8, o8, b2_8);
    }
    cudaEventRecord(evb[0], st[0]);

    /* s = 4 on st[1] */
    cudaStreamWaitEvent(st[1], ev0, 0);
    {
        const int Ls = 256;
        ema_kernel<__half, __half, 256><<<ROWS / 8, 256, 0, st[1]>>>(d4, d4 + (size_t)ROWS * Ls, al4, 0, 0);
        gemm1_kernel<<<dim3(8, 128), 256, GEMM_SMEM_B, st[1]>>>(d4, w1h4, h4, b1_4, Ls,
                                                                means + ROWS, wbar + 1024);
        cudaEventRecord(evg[1], st[1]);
        gemm2_kernel<<<dim3(8, 128), 256, GEMM_SMEM_B, st[1]>>>(h4, w2h4, o4, b2_4);
    }
    cudaEventRecord(evb[1], st[1]);

    /* s = 2 on st[2] */
    cudaStreamWaitEvent(st[2], ev0, 0);
    {
        const int Ls = 512;
        ema_kernel<__half, __half, 512><<<ROWS / 8, 256, 0, st[2]>>>(d2, d2 + (size_t)ROWS * Ls, al2, 0, 0);
        gemm1_kernel<<<dim3(8, 128), 256, GEMM_SMEM_B, st[2]>>>(d2, w1h2, h2, b1_2, Ls,
                                                                means + 2 * ROWS, wbar + 2048);
        cudaEventRecord(evg[2], st[2]);
        gemm2_kernel<<<dim3(8, 128), 256, GEMM_SMEM_B, st[2]>>>(h2, w2h2, o2, b2_2);
    }
    cudaEventRecord(evb[2], st[2]);

    /* gates only need GEMM1 results — concurrent with GEMM2s */
    for (int i = 0; i < 3; i++)
        cudaStreamWaitEvent(0, evg[i], 0);
    gate_kernel<<<BATCH, 128>>>(gw8, gb8, gw4, gb4, gw2, gb2, gw1, gb1);

    for (int i = 0; i < 3; i++)
        cudaStreamWaitEvent(0, evb[i], 0);
    combine_kernel<<<(NELEM / 8 + 255) / 256, 256>>>(out);
}

// round 17
// speedup vs baseline: 1.0916x; 1.0916x over previous
#include <cuda_runtime.h>
#include <cuda_fp16.h>
#include <math.h>
#include <stdint.h>

#define BATCH 64
#define CH    128
#define LEN   1024
#define ROWS  (BATCH*CH)          /* 8192  */
#define FEAT  (CH*LEN)            /* 131072 */
#define NELEM (BATCH*CH*LEN)      /* 8388608 */

/* ---------------- scratch (static device globals; allocation-free) -------- */
__device__ float  g_xn[NELEM];
__device__ __half g_trend1[NELEM];
__device__ __half g_d8[2 * ROWS * 128];
__device__ __half g_d4[2 * ROWS * 256];
__device__ __half g_d2[2 * ROWS * 512];
__device__ __half g_h8[2 * ROWS * LEN];
__device__ __half g_h4[2 * ROWS * LEN];
__device__ __half g_h2[2 * ROWS * LEN];
__device__ __half g_o8[2 * ROWS * LEN];        /* [up ; trend], half          */
__device__ __half g_o4[2 * ROWS * LEN];
__device__ __half g_o2[2 * ROWS * LEN];
__device__ float  g_means[5 * ROWS];     /* [mdiff8|mdiff4|mdiff2|sx1|sy1]   */
__device__ float  g_gates[BATCH * 4];
__device__ float  g_wbar[3 * 1024];      /* col-means of w2 (incl 1/L)       */
__device__ __half g_w1h[1024 * (512 + 256 + 128)];
__device__ __half g_w2h[3 * 1024 * 1024];

/* ------ prep: weights->half, zero mdiff, wbar (block-range dispatch) ------- */
#define NW_TOTAL (1024*(512+256+128) + 3*1024*1024)      /* 4063232 */
#define PREP_CONV_BLOCKS ((NW_TOTAL + 255) / 256)        /* 15872   */
#define PREP_WBAR_BLOCKS 12
__global__ void prep_kernel(const float* __restrict__ w18, const float* __restrict__ w14,
                            const float* __restrict__ w12, const float* __restrict__ w28,
                            const float* __restrict__ w24, const float* __restrict__ w22) {
    if (blockIdx.x >= PREP_CONV_BLOCKS) {
        int kk = (blockIdx.x - PREP_CONV_BLOCKS) * 256 + threadIdx.x;
        int br = kk >> 10;
        int k  = kk & 1023;
        const float* w = (br == 0) ? w28 : (br == 1) ? w24 : w22;
        float s = 0.f;
        for (int l = 0; l < 1024; l++) s += w[l * 1024 + k];
        g_wbar[kk] = s * (1.f / 1024.f);
        return;
    }
    int i = blockIdx.x * blockDim.x + threadIdx.x;
    if (i < 3 * ROWS) g_means[i] = 0.f;
    if (i >= NW_TOTAL) return;
    float v;
    int j = i;
    __half* dst;
    if (j < 131072)            { v = w18[j];            dst = g_w1h + j; }
    else if (j < 393216)       { v = w14[j - 131072];   dst = g_w1h + j; }
    else if (j < 917504)       { v = w12[j - 393216];   dst = g_w1h + j; }
    else if (j < 1966080)      { v = w28[j - 917504];   dst = g_w2h + (j - 917504); }
    else if (j < 3014656)      { v = w24[j - 1966080];  dst = g_w2h + (j - 917504); }
    else                       { v = w22[j - 3014656];  dst = g_w2h + (j - 917504); }
    *dst = __float2half_rn(v);
}

/* ---------------- BatchNorm over batch axis ------------------------------- */
__global__ void bn_kernel(const float* __restrict__ x,
                          const float* __restrict__ gam,
                          const float* __restrict__ bet) {
    int f = blockIdx.x * blockDim.x + threadIdx.x;
    if (f >= FEAT) return;
    float v[BATCH];
    float s = 0.f;
#pragma unroll
    for (int b = 0; b < BATCH; b++) { v[b] = x[(size_t)b * FEAT + f]; s += v[b]; }
    float mu = s * (1.f / BATCH);
    float q = 0.f;
#pragma unroll
    for (int b = 0; b < BATCH; b++) { float d = v[b] - mu; q += d * d; }
    float inv = rsqrtf(q * (1.f / BATCH) + 1e-5f);
    float gg = gam[f] * inv, bb = bet[f];
#pragma unroll
    for (int b = 0; b < BATCH; b++)
        g_xn[(size_t)b * FEAT + f] = (v[b] - mu) * gg + bb;
}

/* ---------------- fused depthwise conv, smem-staged ------------------------ */
__global__ void __launch_bounds__(256)
dwconv_all_kernel(const float* __restrict__ xn,
                  const float* __restrict__ cw8,
                  const float* __restrict__ cw4,
                  const float* __restrict__ cw2,
                  __half* __restrict__ o8,
                  __half* __restrict__ o4,
                  __half* __restrict__ o2) {
    __shared__ float sx[2][LEN + 16];
    const int tid = threadIdx.x;
    const int r   = tid >> 7;
    const int t8  = tid & 127;
    const int row = blockIdx.x * 2 + r;
    const int c   = row & (CH - 1);

    {
        const float4* src = (const float4*)(xn + (size_t)row * LEN);
        float4* dstv = (float4*)(sx[r] + 4);
#pragma unroll
        for (int q = 0; q < 2; q++)
            dstv[t8 + q * 128] = src[t8 + q * 128];
        if (t8 < 4)  sx[r][t8] = 0.f;
        if (t8 < 12) sx[r][LEN + 4 + t8] = 0.f;
    }
    __syncthreads();

    const float* w = sx[r] + t8 * 8;
    {
        const float* cf = cw8 + c * 16;
        float acc = 0.f;
#pragma unroll
        for (int k = 0; k < 16; k++) acc = fmaf(w[k], cf[k], acc);
        o8[(size_t)row * 128 + t8] = __float2half_rn(acc);
    }
    {
        const float* cf = cw4 + c * 8;
#pragma unroll
        for (int i = 0; i < 2; i++) {
            float acc = 0.f;
#pragma unroll
            for (int k = 0; k < 8; k++) acc = fmaf(w[2 + 4 * i + k], cf[k], acc);
            o4[(size_t)row * 256 + 2 * t8 + i] = __float2half_rn(acc);
        }
    }
    {
        const float* cf = cw2 + c * 4;
#pragma unroll
        for (int i = 0; i < 4; i++) {
            float acc = 0.f;
#pragma unroll
            for (int k = 0; k < 4; k++) acc = fmaf(w[3 + 2 * i + k], cf[k], acc);
            o2[(size_t)row * 512 + 4 * t8 + i] = __float2half_rn(acc);
        }
    }
}

/* ---------------- EMA: chunked scan + closed-form den (round-14 proven) ---- */
template <typename TI, typename TO>
__global__ void ema_kernel(const TI* __restrict__ src,
                           TO* __restrict__ dst,
                           const float* __restrict__ al, int Ls,
                           float* __restrict__ sumx, float* __restrict__ sumy) {
    int warp = (blockIdx.x * blockDim.x + threadIdx.x) >> 5;
    int lane = threadIdx.x & 31;
    if (warp >= ROWS) return;
    int c = warp % CH;
    float a  = 1.f / (1.f + expf(-al[c]));
    float om = 1.f - a;
    float l2 = log2f(om);
    float inva = 1.f / a;
    float pl = exp2f((float)(31 - lane) * l2);
    float K0 = exp2f((float)Ls * l2);
    const TI* x = src + (size_t)warp * Ls;
    TO* y       = dst + (size_t)warp * Ls;
    float cnum = 0.f, sx = 0.f, sy = 0.f;
    for (int j0 = 0; j0 < Ls; j0 += 32) {
        int j = j0 + lane;
        float cc = exp2f((float)(Ls - 32 - j0) * l2);
        float base = cc * pl;
        float wn = (j == 0) ? base : base * a;
        float xv = (float)x[j];
        float n = xv * wn;
#pragma unroll
        for (int o = 1; o < 32; o <<= 1) {
            float nn = __shfl_up_sync(0xffffffffu, n, o);
            if (lane >= o) n += nn;
        }
        n += cnum;
        float den = fmaxf((base - K0) * inva, 1e-12f);
        float yv = n / den;
        y[j] = (TO)yv;
        sx += xv; sy += yv;
        cnum = __shfl_sync(0xffffffffu, n, 31);
    }
    if (sumx) {
#pragma unroll
        for (int o = 16; o > 0; o >>= 1) {
            sx += __shfl_xor_sync(0xffffffffu, sx, o);
            sy += __shfl_xor_sync(0xffffffffu, sy, o);
        }
        if (lane == 0) { sumx[warp] = sx; sumy[warp] = sy; }
    }
}

/* =================== shared GEMM machinery ================================== */
#define PITCH_H 72
#define PITCH_B 144
#define BKH 64
#define MAT_STAGE_B 18432
#define B_OFF 36864
#define GEMM_SMEM_B 73728

__device__ __forceinline__ uint32_t smem_u32(const void* p) {
    uint32_t a;
    asm("{.reg .u64 t; cvta.to.shared.u64 t, %1; cvt.u32.u64 %0, t;}"
        : "=r"(a) : "l"(p));
    return a;
}
__device__ __forceinline__ void cp_async16(uint32_t saddr, const void* g) {
    asm volatile("cp.async.cg.shared.global [%0], [%1], 16;"
                 :: "r"(saddr), "l"(g));
}
#define LDSM4(r0, r1, r2, r3, addr) \
    asm volatile("ldmatrix.sync.aligned.m8n8.x4.shared.b16 {%0,%1,%2,%3}, [%4];" \
                 : "=r"(r0), "=r"(r1), "=r"(r2), "=r"(r3) : "r"(addr))

__device__ __forceinline__ void mma_f16(float* d,
                                        const uint32_t* a, const uint32_t* b,
                                        const float* c) {
    asm volatile(
        "mma.sync.aligned.m16n8k16.row.col.f32.f16.f16.f32 "
        "{%0,%1,%2,%3}, {%4,%5,%6,%7}, {%8,%9}, {%10,%11,%12,%13};"
        : "=f"(d[0]), "=f"(d[1]), "=f"(d[2]), "=f"(d[3])
        : "r"(a[0]), "r"(a[1]), "r"(a[2]), "r"(a[3]),
          "r"(b[0]), "r"(b[1]),
          "f"(c[0]), "f"(c[1]), "f"(c[2]), "f"(c[3]));
}

__device__ __forceinline__ float gelu_exact(float v) {
    return 0.5f * v * (1.f + erff(v * 0.70710678118654752f));
}

__device__ __forceinline__ void mma_step(const uint32_t aa, const uint32_t bb,
                                         float acc[2][8][4]) {
#pragma unroll
    for (int kk = 0; kk < 4; kk++) {
        const uint32_t kb = kk * 32;
        uint32_t af[2][4], bf[8][2];
        LDSM4(af[0][0], af[0][1], af[0][2], af[0][3], aa + kb);
        LDSM4(af[1][0], af[1][1], af[1][2], af[1][3], aa + kb + 16 * PITCH_B);
#pragma unroll
        for (int p = 0; p < 4; p++) {
            uint32_t q0, q1, q2, q3;
            LDSM4(q0, q1, q2, q3, bb + kb + p * 16 * PITCH_B);
            bf[2 * p][0] = q0; bf[2 * p + 1][0] = q1;
            bf[2 * p][1] = q2; bf[2 * p + 1][1] = q3;
        }
#pragma unroll
        for (int mt = 0; mt < 2; mt++)
#pragma unroll
            for (int nt = 0; nt < 8; nt++)
                mma_f16(acc[mt][nt], af[mt], bf[nt], acc[mt][nt]);
    }
}

#define GEMM_MAINLOOP(src, sldbase, a_ab, b_ab, niter, acc)                     \
    do {                                                                        \
        _Pragma("unroll")                                                       \
        for (int c = 0; c < 8; c++)                                             \
            cp_async16((sldbase) + c * 16, (src) + c * 8);                      \
        asm volatile("cp.async.commit_group;");                                 \
        for (int i = 0; i < (niter); i++) {                                     \
            asm volatile("cp.async.wait_group 0;");                             \
            __syncthreads();                                                    \
            if (i + 1 < (niter)) {                                              \
                const __half* gsrc = (src) + (i + 1) * BKH;                     \
                uint32_t d = ((i + 1) & 1) * MAT_STAGE_B;                       \
                _Pragma("unroll")                                               \
                for (int c = 0; c < 8; c++)                                     \
                    cp_async16((sldbase) + d + c * 16, gsrc + c * 8);           \
                asm volatile("cp.async.commit_group;");                         \
            }                                                                   \
            const uint32_t stg = (i & 1) * MAT_STAGE_B;                         \
            mma_step((a_ab) + stg, (b_ab) + stg, acc);                          \
        }                                                                       \
    } while (0)

/* ============ GEMM1: h = gelu(A·W1^T + b1), + signed w̄2 row-reduce ========= */
__global__ void __launch_bounds__(256, 2)
gemm1_kernel(const __half* __restrict__ A, const __half* __restrict__ B,
             __half* __restrict__ Cout, const float* __restrict__ bias,
             int K, float* __restrict__ mdiff, const float* __restrict__ wbar) {
    extern __shared__ char smem[];
    const uint32_t sb = smem_u32(smem);
    const int tid  = threadIdx.x;
    const int wid  = tid >> 5;
    const int lane = tid & 31;
    const int g    = lane >> 2;
    const int tg   = lane & 3;
    const int wm   = (wid >> 1) * 32;
    const int wn   = (wid & 1) * 64;
    const int m0 = blockIdx.y * 128, n0 = blockIdx.x * 128;

    const int mat = tid >> 7, row = tid & 127;
    const __half* src = mat ? (B + (size_t)(n0 + row) * K)
                            : (A + (size_t)(m0 + row) * K);
    const uint32_t sldbase = sb + mat * B_OFF + row * PITCH_B;

    const int lr16 = lane & 15;
    const int lhi  = (lane >> 4) << 3;
    const uint32_t a_ab = sb + ((wm + lr16) * PITCH_H + lhi) * 2;
    const uint32_t b_ab = sb + B_OFF + ((wn + lr16) * PITCH_H + lhi) * 2;

    float acc[2][8][4];
#pragma unroll
    for (int i = 0; i < 2; i++)
#pragma unroll
        for (int j = 0; j < 8; j++)
#pragma unroll
            for (int q = 0; q < 4; q++) acc[i][j][q] = 0.f;

    const int niter = K / BKH;
    GEMM_MAINLOOP(src, sldbase, a_ab, b_ab, niter, acc);

#pragma unroll
    for (int mt = 0; mt < 2; mt++) {
        int r0 = m0 + wm + mt * 16 + g;
        float sgn = (r0 < ROWS) ? 1.f : -1.f;
        int srow = r0 & (ROWS - 1);
        float d0 = 0.f, d1 = 0.f;
#pragma unroll
        for (int nt = 0; nt < 8; nt++) {
            int c0 = n0 + wn + nt * 8 + 2 * tg;
            float b0 = bias[c0], b1 = bias[c0 + 1];
            float v0 = gelu_exact(acc[mt][nt][0] + b0);
            float v1 = gelu_exact(acc[mt][nt][1] + b1);
            float v2 = gelu_exact(acc[mt][nt][2] + b0);
            float v3 = gelu_exact(acc[mt][nt][3] + b1);
            float wb0 = wbar[c0], wb1 = wbar[c0 + 1];
            d0 += wb0 * v0 + wb1 * v1;
            d1 += wb0 * v2 + wb1 * v3;
            *(__half2*)(Cout + (size_t)r0 * 1024 + c0)       = __floats2half2_rn(v0, v1);
            *(__half2*)(Cout + (size_t)(r0 + 8) * 1024 + c0) = __floats2half2_rn(v2, v3);
        }
        d0 += __shfl_xor_sync(0xffffffffu, d0, 1);
        d0 += __shfl_xor_sync(0xffffffffu, d0, 2);
        d1 += __shfl_xor_sync(0xffffffffu, d1, 1);
        d1 += __shfl_xor_sync(0xffffffffu, d1, 2);
        if (tg == 0) {
            atomicAdd(&mdiff[srow],     sgn * d0);
            atomicAdd(&mdiff[srow + 8], sgn * d1);
        }
    }
}

/* ============ GEMM2: o = A·W2^T + b2  (half out) ============================ */
__global__ void __launch_bounds__(256, 2)
gemm2_kernel(const __half* __restrict__ A, const __half* __restrict__ B,
             __half* __restrict__ Cout, const float* __restrict__ bias) {
    extern __shared__ char smem[];
    const uint32_t sb = smem_u32(smem);
    const int tid  = threadIdx.x;
    const int wid  = tid >> 5;
    const int lane = tid & 31;
    const int g    = lane >> 2;
    const int tg   = lane & 3;
    const int wm   = (wid >> 1) * 32;
    const int wn   = (wid & 1) * 64;
    const int m0 = blockIdx.y * 128, n0 = blockIdx.x * 128;
    const int K = 1024;

    const int mat = tid >> 7, row = tid & 127;
    const __half* src = mat ? (B + (size_t)(n0 + row) * K)
                            : (A + (size_t)(m0 + row) * K);
    const uint32_t sldbase = sb + mat * B_OFF + row * PITCH_B;

    const int lr16 = lane & 15;
    const int lhi  = (lane >> 4) << 3;
    const uint32_t a_ab = sb + ((wm + lr16) * PITCH_H + lhi) * 2;
    const uint32_t b_ab = sb + B_OFF + ((wn + lr16) * PITCH_H + lhi) * 2;

    float acc[2][8][4];
#pragma unroll
    for (int i = 0; i < 2; i++)
#pragma unroll
        for (int j = 0; j < 8; j++)
#pragma unroll
            for (int q = 0; q < 4; q++) acc[i][j][q] = 0.f;

    GEMM_MAINLOOP(src, sldbase, a_ab, b_ab, 16, acc);

#pragma unroll
    for (int mt = 0; mt < 2; mt++) {
        int r0 = m0 + wm + mt * 16 + g;
#pragma unroll
        for (int nt = 0; nt < 8; nt++) {
            int c0 = n0 + wn + nt * 8 + 2 * tg;
            float b0 = bias[c0], b1 = bias[c0 + 1];
            *(__half2*)(Cout + (size_t)r0 * 1024 + c0) =
                __floats2half2_rn(acc[mt][nt][0] + b0, acc[mt][nt][1] + b1);
            *(__half2*)(Cout + (size_t)(r0 + 8) * 1024 + c0) =
                __floats2half2_rn(acc[mt][nt][2] + b0, acc[mt][nt][3] + b1);
        }
    }
}

/* ---------------- gates ----------------------------------------------------- */
__global__ void gate_kernel(const float* __restrict__ gw8, const float* __restrict__ gb8,
                            const float* __restrict__ gw4, const float* __restrict__ gb4,
                            const float* __restrict__ gw2, const float* __restrict__ gb2,
                            const float* __restrict__ gw1, const float* __restrict__ gb1) {
    int b = blockIdx.x;
    int c = threadIdx.x;
    __shared__ float red[4][128];
    int bc = b * CH + c;
    red[0][c] = g_means[bc] * gw8[c];
    red[1][c] = g_means[ROWS + bc] * gw4[c];
    red[2][c] = g_means[2 * ROWS + bc] * gw2[c];
    red[3][c] = (g_means[3 * ROWS + bc] - g_means[4 * ROWS + bc]) * (1.f / LEN) * gw1[c];
    __syncthreads();
    for (int o = 64; o > 0; o >>= 1) {
        if (c < o) {
            for (int s = 0; s < 4; s++) red[s][c] += red[s][c + o];
        }
        __syncthreads();
    }
    if (c == 0) {
        float gbv[4] = {gb8[0], gb4[0], gb2[0], gb1[0]};
        float gv[4], tot = 0.f;
        for (int s = 0; s < 4; s++) {
            gv[s] = 1.f / (1.f + expf(-(red[s][0] + gbv[s])));
            tot += gv[s];
        }
        for (int s = 0; s < 4; s++) g_gates[b * 4 + s] = gv[s] / (tot + 1e-6f);
    }
}

/* ---------------- vectorized combine: 8 elems/thread ----------------------- */
__global__ void combine_kernel(float* __restrict__ out) {
    size_t t = blockIdx.x * (size_t)blockDim.x + threadIdx.x;
    size_t i8 = t * 8;
    if (i8 >= NELEM) return;
    int b = (int)(i8 >> 10) / CH;
    const float* G = g_gates + b * 4;
    float g0 = G[0], g1 = G[1], g2 = G[2], g3 = G[3];

    const __half2* u8p = (const __half2*)(g_o8 + i8);
    const __half2* t8p = (const __half2*)(g_o8 + (size_t)NELEM + i8);
    const __half2* u4p = (const __half2*)(g_o4 + i8);
    const __half2* t4p = (const __half2*)(g_o4 + (size_t)NELEM + i8);
    const __half2* u2p = (const __half2*)(g_o2 + i8);
    const __half2* t2p = (const __half2*)(g_o2 + (size_t)NELEM + i8);
    const __half2* t1p = (const __half2*)(g_trend1 + i8);

    float x1[8];
    *(float4*)(x1)     = *(const float4*)(g_xn + i8);
    *(float4*)(x1 + 4) = *(const float4*)(g_xn + i8 + 4);

    float se[8], tr[8];
#pragma unroll
    for (int q = 0; q < 4; q++) {
        float2 u8v = __half22float2(u8p[q]);
        float2 t8v = __half22float2(t8p[q]);
        float2 u4v = __half22float2(u4p[q]);
        float2 t4v = __half22float2(t4p[q]);
        float2 u2v = __half22float2(u2p[q]);
        float2 t2v = __half22float2(t2p[q]);
        float2 t1v = __half22float2(t1p[q]);
        tr[2 * q]     = g0 * t8v.x + g1 * t4v.x + g2 * t2v.x + g3 * t1v.x;
        tr[2 * q + 1] = g0 * t8v.y + g1 * t4v.y + g2 * t2v.y + g3 * t1v.y;
        se[2 * q]     = g0 * (u8v.x - t8v.x) + g1 * (u4v.x - t4v.x)
                      + g2 * (u2v.x - t2v.x) + g3 * (x1[2 * q] - t1v.x);
        se[2 * q + 1] = g0 * (u8v.y - t8v.y) + g1 * (u4v.y - t4v.y)
                      + g2 * (u2v.y - t2v.y) + g3 * (x1[2 * q + 1] - t1v.y);
    }
    *(float4*)(out + i8)                       = *(float4*)(se);
    *(float4*)(out + i8 + 4)                   = *(float4*)(se + 4);
    *(float4*)(out + (size_t)NELEM + i8)       = *(float4*)(tr);
    *(float4*)(out + (size_t)NELEM + i8 + 4)   = *(float4*)(tr + 4);
}

/* ---------------- host orchestration -------------------------------------- */
extern "C" void kernel_launch(void* const* d_in, const int* in_sizes, int n_in,
                              void* d_out, int out_size) {
    const float* x    = (const float*)d_in[0];
    const float* bng  = (const float*)d_in[1];
    const float* bnb  = (const float*)d_in[2];
    const float* cw8  = (const float*)d_in[3];
    const float* w1_8 = (const float*)d_in[4];
    const float* b1_8 = (const float*)d_in[5];
    const float* w2_8 = (const float*)d_in[6];
    const float* b2_8 = (const float*)d_in[7];
    const float* cw4  = (const float*)d_in[8];
    const float* w1_4 = (const float*)d_in[9];
    const float* b1_4 = (const float*)d_in[10];
    const float* w2_4 = (const float*)d_in[11];
    const float* b2_4 = (const float*)d_in[12];
    const float* cw2  = (const float*)d_in[13];
    const float* w1_2 = (const float*)d_in[14];
    const float* b1_2 = (const float*)d_in[15];
    const float* w2_2 = (const float*)d_in[16];
    const float* b2_2 = (const float*)d_in[17];
    const float* gw8  = (const float*)d_in[18];
    const float* gb8  = (const float*)d_in[19];
    const float* al8  = (const float*)d_in[20];
    const float* gw4  = (const float*)d_in[21];
    const float* gb4  = (const float*)d_in[22];
    const float* al4  = (const float*)d_in[23];
    const float* gw2  = (const float*)d_in[24];
    const float* gb2  = (const float*)d_in[25];
    const float* al2  = (const float*)d_in[26];
    const float* gw1  = (const float*)d_in[27];
    const float* gb1  = (const float*)d_in[28];
    const float* al1  = (const float*)d_in[29];
    float* out = (float*)d_out;

    float *xn, *means, *wbar;
    __half *tr1, *d8, *d4, *d2, *h8, *h4, *h2, *o8, *o4, *o2, *w1h, *w2h;
    cudaGetSymbolAddress((void**)&xn,    g_xn);
    cudaGetSymbolAddress((void**)&tr1,   g_trend1);
    cudaGetSymbolAddress((void**)&d8,    g_d8);
    cudaGetSymbolAddress((void**)&d4,    g_d4);
    cudaGetSymbolAddress((void**)&d2,    g_d2);
    cudaGetSymbolAddress((void**)&h8,    g_h8);
    cudaGetSymbolAddress((void**)&h4,    g_h4);
    cudaGetSymbolAddress((void**)&h2,    g_h2);
    cudaGetSymbolAddress((void**)&o8,    g_o8);
    cudaGetSymbolAddress((void**)&o4,    g_o4);
    cudaGetSymbolAddress((void**)&o2,    g_o2);
    cudaGetSymbolAddress((void**)&means, g_means);
    cudaGetSymbolAddress((void**)&wbar,  g_wbar);
    cudaGetSymbolAddress((void**)&w1h,   g_w1h);
    cudaGetSymbolAddress((void**)&w2h,   g_w2h);

    __half* w1h8 = w1h;
    __half* w1h4 = w1h + 1024 * 128;
    __half* w1h2 = w1h + 1024 * (128 + 256);
    __half* w2h8 = w2h;
    __half* w2h4 = w2h + 1024 * 1024;
    __half* w2h2 = w2h + 2 * 1024 * 1024;

    cudaFuncSetAttribute(gemm1_kernel,
                         cudaFuncAttributeMaxDynamicSharedMemorySize, GEMM_SMEM_B);
    cudaFuncSetAttribute(gemm2_kernel,
                         cudaFuncAttributeMaxDynamicSharedMemorySize, GEMM_SMEM_B);

    static cudaStream_t st[3];
    static cudaEvent_t  ev0, evg[3], evb[3];
    static int sinit = 0;
    if (!sinit) {
        for (int i = 0; i < 3; i++)
            cudaStreamCreateWithFlags(&st[i], cudaStreamNonBlocking);
        cudaEventCreateWithFlags(&ev0, cudaEventDisableTiming);
        for (int i = 0; i < 3; i++) {
            cudaEventCreateWithFlags(&evg[i], cudaEventDisableTiming);
            cudaEventCreateWithFlags(&evb[i], cudaEventDisableTiming);
        }
        sinit = 1;
    }

    /* ---- head: prep overlaps bn+dwconv via event-object reuse ----
       evg[0] record #1 = root fork; evb[0] record #1 = weights-done.
       Waits bind to the most recent record at CALL time, so st[1]/st[2]
       weight-waits are issued BEFORE the objects are re-recorded in their
       normal roles. 3 streams / 7 event objects (proven envelope). */
    cudaEventRecord(evg[0], 0);                       /* root */
    cudaStreamWaitEvent(st[0], evg[0], 0);            /* fork st0 */
    prep_kernel<<<PREP_CONV_BLOCKS + PREP_WBAR_BLOCKS, 256, 0, st[0]>>>(
        w1_8, w1_4, w1_2, w2_8, w2_4, w2_2);
    cudaEventRecord(evb[0], st[0]);                   /* weights-done */
    cudaStreamWaitEvent(st[1], evb[0], 0);            /* binds weights rec */
    cudaStreamWaitEvent(st[2], evb[0], 0);

    /* data-side head on default stream, overlapping prep */
    bn_kernel<<<FEAT / 256, 256>>>(x, bng, bnb);
    dwconv_all_kernel<<<ROWS / 2, 256>>>(xn, cw8, cw4, cw2, d8, d4, d2);
    cudaEventRecord(ev0, 0);

    /* s=1 branch on default stream (hidden behind branch GEMMs) */
    ema_kernel<float, __half><<<ROWS / 8, 256>>>(xn, tr1, al1, LEN,
                                                 means + 3 * ROWS,
                                                 means + 4 * ROWS);

    /* s = 8 on st[0] (weights in-stream after prep) */
    cudaStreamWaitEvent(st[0], ev0, 0);
    {
        const int Ls = 128;
        ema_kernel<__half, __half><<<ROWS / 8, 256, 0, st[0]>>>(d8, d8 + (size_t)ROWS * Ls, al8, Ls, 0, 0);
        gemm1_kernel<<<dim3(8, 128), 256, GEMM_SMEM_B, st[0]>>>(d8, w1h8, h8, b1_8, Ls,
                                                                means, wbar);
        cudaEventRecord(evg[0], st[0]);               /* re-record: real g0 */
        gemm2_kernel<<<dim3(8, 128), 256, GEMM_SMEM_B, st[0]>>>(h8, w2h8, o8, b2_8);
    }
    cudaEventRecord(evb[0], st[0]);                   /* re-record: real b0 */

    /* s = 4 on st[1] */
    cudaStreamWaitEvent(st[1], ev0, 0);
    {
        const int Ls = 256;
        ema_kernel<__half, __half><<<ROWS / 8, 256, 0, st[1]>>>(d4, d4 + (size_t)ROWS * Ls, al4, Ls, 0, 0);
        gemm1_kernel<<<dim3(8, 128), 256, GEMM_SMEM_B, st[1]>>>(d4, w1h4, h4, b1_4, Ls,
                                                                means + ROWS, wbar + 1024);
        cudaEventRecord(evg[1], st[1]);
        gemm2_kernel<<<dim3(8, 128), 256, GEMM_SMEM_B, st[1]>>>(h4, w2h4, o4, b2_4);
    }
    cudaEventRecord(evb[1], st[1]);

    /* s = 2 on st[2] */
    cudaStreamWaitEvent(st[2], ev0, 0);
    {
        const int Ls = 512;
        ema_kernel<__half, __half><<<ROWS / 8, 256, 0, st[2]>>>(d2, d2 + (size_t)ROWS * Ls, al2, Ls, 0, 0);
        gemm1_kernel<<<dim3(8, 128), 256, GEMM_SMEM_B, st[2]>>>(d2, w1h2, h2, b1_2, Ls,
                                                                means + 2 * ROWS, wbar + 2048);
        cudaEventRecord(evg[2], st[2]);
        gemm2_kernel<<<dim3(8, 128), 256, GEMM_SMEM_B, st[2]>>>(h2, w2h2, o2, b2_2);
    }
    cudaEventRecord(evb[2], st[2]);

    /* gates only need GEMM1 results — concurrent with GEMM2s */
    for (int i = 0; i < 3; i++)
        cudaStreamWaitEvent(0, evg[i], 0);            /* binds latest (real) recs */
    gate_kernel<<<BATCH, 128>>>(gw8, gb8, gw4, gb4, gw2, gb2, gw1, gb1);

    for (int i = 0; i < 3; i++)
        cudaStreamWaitEvent(0, evb[i], 0);
    combine_kernel<<<(NELEM / 8 + 255) / 256, 256>>>(out);
}